// round 16
// baseline (speedup 1.0000x reference)
#include <cuda_runtime.h>
#include <cuda_bf16.h>
#include <math.h>
#include <stdint.h>

#define T_   2048
#define B_   2
#define S_   2048
#define E_   1024
#define H_   16
#define HD_  64
#define R_   16
#define NROW 4096
#define LDQ  (B_*E_)
#define SCALE 0.125f

// ---------------- scratch (static device globals; no allocs allowed) --------
__device__ float g_ao[(size_t)NROW * E_];
__device__ float g_t [NROW * R_];
__device__ float g_probs[(size_t)B_ * H_ * T_ * S_];            // 512 MB fp32 scores
__device__ __nv_bfloat16 g_phi[(size_t)B_ * H_ * T_ * S_];      // 256 MB
__device__ __nv_bfloat16 g_plo[(size_t)B_ * H_ * T_ * S_];      // 256 MB
__device__ __nv_bfloat16 g_ahi[(size_t)NROW * E_];
__device__ __nv_bfloat16 g_alo[(size_t)NROW * E_];
__device__ __nv_bfloat16 g_whi[(size_t)E_ * E_];
__device__ __nv_bfloat16 g_wlo[(size_t)E_ * E_];
__device__ __nv_bfloat16 g_qhi[(size_t)NROW * E_];
__device__ __nv_bfloat16 g_qlo[(size_t)NROW * E_];
__device__ __nv_bfloat16 g_khi[(size_t)NROW * E_];
__device__ __nv_bfloat16 g_klo[(size_t)NROW * E_];
__device__ __nv_bfloat16 g_vhi[(size_t)NROW * E_];
__device__ __nv_bfloat16 g_vlo[(size_t)NROW * E_];

// =================== portable tensor-core helpers ==========================
__device__ __forceinline__ uint32_t smem_u32(const void* p) {
    uint32_t a;
    asm("{ .reg .u64 t; cvta.to.shared.u64 t, %1; cvt.u32.u64 %0, t; }"
        : "=r"(a) : "l"(p));
    return a;
}

#define LDSM_X4(r0, r1, r2, r3, addr) \
    asm volatile("ldmatrix.sync.aligned.m8n8.x4.shared.b16 {%0,%1,%2,%3}, [%4];" \
                 : "=r"(r0), "=r"(r1), "=r"(r2), "=r"(r3) : "r"(addr))

#define LDSM_X4_T(r0, r1, r2, r3, addr) \
    asm volatile("ldmatrix.sync.aligned.m8n8.x4.trans.shared.b16 {%0,%1,%2,%3}, [%4];" \
                 : "=r"(r0), "=r"(r1), "=r"(r2), "=r"(r3) : "r"(addr))

#define MMA_BF16(d, a, b0v, b1v) \
    asm volatile("mma.sync.aligned.m16n8k16.row.col.f32.bf16.bf16.f32 " \
                 "{%0,%1,%2,%3}, {%4,%5,%6,%7}, {%8,%9}, {%0,%1,%2,%3};" \
                 : "+f"((d)[0]), "+f"((d)[1]), "+f"((d)[2]), "+f"((d)[3]) \
                 : "r"((a)[0]), "r"((a)[1]), "r"((a)[2]), "r"((a)[3]), \
                   "r"(b0v), "r"(b1v))

// =================== fp32 -> (bf16 hi, bf16 lo) ============================
__global__ void __launch_bounds__(256) cvt_hilo_kernel(
    const float* __restrict__ x,
    __nv_bfloat16* __restrict__ hi, __nv_bfloat16* __restrict__ lo)
{
    size_t i = ((size_t)blockIdx.x * 256 + threadIdx.x) * 4;
    float4 v = *(const float4*)(x + i);
    __nv_bfloat16 h0 = __float2bfloat16(v.x);
    __nv_bfloat16 h1 = __float2bfloat16(v.y);
    __nv_bfloat16 h2 = __float2bfloat16(v.z);
    __nv_bfloat16 h3 = __float2bfloat16(v.w);
    __nv_bfloat16 l0 = __float2bfloat16(v.x - __bfloat162float(h0));
    __nv_bfloat16 l1 = __float2bfloat16(v.y - __bfloat162float(h1));
    __nv_bfloat16 l2 = __float2bfloat16(v.z - __bfloat162float(h2));
    __nv_bfloat16 l3 = __float2bfloat16(v.w - __bfloat162float(h3));
    __nv_bfloat162* hp = (__nv_bfloat162*)(hi + i);
    __nv_bfloat162* lp = (__nv_bfloat162*)(lo + i);
    __nv_bfloat162 a; a.x = h0; a.y = h1; hp[0] = a;
    __nv_bfloat162 b; b.x = h2; b.y = h3; hp[1] = b;
    __nv_bfloat162 c; c.x = l0; c.y = l1; lp[0] = c;
    __nv_bfloat162 d; d.x = l2; d.y = l3; lp[1] = d;
}

// =================== mma.sync LoRA GEMM ====================================
#define BK      32
#define NCHUNK  (E_ / BK)          // 32
#define TILE_B  (128 * 80)         // 10240 B (rows padded to 80 B)
#define BUF_B   (4 * TILE_B)       // 40960 B per stage
#define GM_SMEM (2 * BUF_B)        // 81920 B

__global__ void __launch_bounds__(256) gemm_lora_mma(
    const __nv_bfloat16* __restrict__ Ahi, const __nv_bfloat16* __restrict__ Alo,
    const __nv_bfloat16* __restrict__ Whi, const __nv_bfloat16* __restrict__ Wlo,
    const float* __restrict__ bias, const float* __restrict__ lb,
    const float* __restrict__ t, float* __restrict__ C,
    __nv_bfloat16* __restrict__ Chi, __nv_bfloat16* __restrict__ Clo,
    float oscale)
{
    extern __shared__ __align__(128) char smem[];
    const uint32_t sb = smem_u32(smem);
    int tid = threadIdx.x, wid = tid >> 5, lane = tid & 31;
    int m0 = blockIdx.x * 128, n0 = blockIdx.y * 128;
    int wm = wid >> 2, wn = wid & 3;      // warp tile: 64 rows x 32 cols

    const __nv_bfloat16* bases[4] = {
        Ahi + (size_t)m0 * E_, Alo + (size_t)m0 * E_,
        Whi + (size_t)n0 * E_, Wlo + (size_t)n0 * E_ };

    auto load_chunk = [&](int c, int buf) {
        int k0 = c * BK;
        #pragma unroll
        for (int l = 0; l < 8; l++) {
            int idx = l * 256 + tid;
            int tI = idx >> 9;
            int r  = (idx >> 2) & 127;
            int ch = idx & 3;
            const __nv_bfloat16* src = bases[tI] + (size_t)r * E_ + k0 + ch * 8;
            uint32_t dst = sb + buf * BUF_B + tI * TILE_B + r * 80 + ch * 16;
            asm volatile("cp.async.cg.shared.global [%0], [%1], 16;"
                         :: "r"(dst), "l"(src));
        }
        asm volatile("cp.async.commit_group;");
    };

    int arow  = lane & 15;
    int acol8 = lane >> 4;
    int brow  = (lane & 7) + ((lane >> 4) & 1) * 8;
    int bcol8 = (lane >> 3) & 1;

    float acc[4][4][4] = {};

    load_chunk(0, 0);
    load_chunk(1, 1);
    asm volatile("cp.async.wait_group 1;");
    __syncthreads();

    for (int c = 0; c < NCHUNK; c++) {
        uint32_t bufb = sb + (c & 1) * BUF_B;
        uint32_t aHiB = bufb, aLoB = bufb + TILE_B;
        uint32_t wHiB = bufb + 2 * TILE_B, wLoB = bufb + 3 * TILE_B;

        #pragma unroll
        for (int s = 0; s < 2; s++) {
            uint32_t ah[4][4], al[4][4], bh[2][4], bl[2][4];
            #pragma unroll
            for (int mt = 0; mt < 4; mt++) {
                uint32_t off = (uint32_t)(wm * 64 + mt * 16 + arow) * 80
                             + (uint32_t)(s * 16 + acol8 * 8) * 2;
                LDSM_X4(ah[mt][0], ah[mt][1], ah[mt][2], ah[mt][3], aHiB + off);
                LDSM_X4(al[mt][0], al[mt][1], al[mt][2], al[mt][3], aLoB + off);
            }
            #pragma unroll
            for (int np = 0; np < 2; np++) {
                uint32_t off = (uint32_t)(wn * 32 + np * 16 + brow) * 80
                             + (uint32_t)(s * 16 + bcol8 * 8) * 2;
                LDSM_X4(bh[np][0], bh[np][1], bh[np][2], bh[np][3], wHiB + off);
                LDSM_X4(bl[np][0], bl[np][1], bl[np][2], bl[np][3], wLoB + off);
            }
            #pragma unroll
            for (int mt = 0; mt < 4; mt++)
                #pragma unroll
                for (int nt = 0; nt < 4; nt++) {
                    uint32_t bh0 = bh[nt >> 1][(nt & 1) * 2];
                    uint32_t bh1 = bh[nt >> 1][(nt & 1) * 2 + 1];
                    uint32_t bl0 = bl[nt >> 1][(nt & 1) * 2];
                    uint32_t bl1 = bl[nt >> 1][(nt & 1) * 2 + 1];
                    MMA_BF16(acc[mt][nt], ah[mt], bh0, bh1);
                    MMA_BF16(acc[mt][nt], ah[mt], bl0, bl1);
                    MMA_BF16(acc[mt][nt], al[mt], bh0, bh1);
                }
        }
        __syncthreads();
        if (c + 2 < NCHUNK) {
            load_chunk(c + 2, c & 1);
            asm volatile("cp.async.wait_group 1;");
        } else {
            asm volatile("cp.async.wait_group 0;");
        }
        __syncthreads();
    }

    // ---- epilogue: bias + t @ lb^T, fused with writeback ----
    float* Ts = (float*)smem;              // 128 x 16
    float* Ls = (float*)(smem + 8192);     // 128 x 16
    float* Bs = (float*)(smem + 16384);    // 128
    #pragma unroll
    for (int l = 0; l < 2; l++) {
        int f = tid + l * 256;
        int r = f >> 2, cc = (f & 3) * 4;
        *(float4*)(Ts + r * R_ + cc) = *(const float4*)(t  + (size_t)(m0 + r) * R_ + cc);
        *(float4*)(Ls + r * R_ + cc) = *(const float4*)(lb + (size_t)(n0 + r) * R_ + cc);
    }
    if (tid < 128) Bs[tid] = bias[n0 + tid];
    __syncthreads();

    int lr = lane >> 2, lc = (lane & 3) * 2;
    #pragma unroll
    for (int mt = 0; mt < 4; mt++) {
        int r0 = wm * 64 + mt * 16 + lr;
        int r1 = r0 + 8;
        float t0[16], t1[16];
        #pragma unroll
        for (int q = 0; q < 4; q++) {
            *(float4*)(t0 + q * 4) = *(const float4*)(Ts + r0 * R_ + q * 4);
            *(float4*)(t1 + q * 4) = *(const float4*)(Ts + r1 * R_ + q * 4);
        }
        #pragma unroll
        for (int nt = 0; nt < 4; nt++) {
            int c0 = wn * 32 + nt * 8 + lc;
            int c1 = c0 + 1;
            float e00 = 0.f, e01 = 0.f, e10 = 0.f, e11 = 0.f;
            #pragma unroll
            for (int r = 0; r < R_; r++) {
                float l0 = Ls[c0 * R_ + r], l1 = Ls[c1 * R_ + r];
                e00 += t0[r] * l0;  e01 += t0[r] * l1;
                e10 += t1[r] * l0;  e11 += t1[r] * l1;
            }
            float v00 = acc[mt][nt][0] + Bs[c0] + e00;
            float v01 = acc[mt][nt][1] + Bs[c1] + e01;
            float v10 = acc[mt][nt][2] + Bs[c0] + e10;
            float v11 = acc[mt][nt][3] + Bs[c1] + e11;
            if (Chi) {
                v00 *= oscale; v01 *= oscale; v10 *= oscale; v11 *= oscale;
                __nv_bfloat16 h00 = __float2bfloat16(v00);
                __nv_bfloat16 h01 = __float2bfloat16(v01);
                __nv_bfloat16 h10 = __float2bfloat16(v10);
                __nv_bfloat16 h11 = __float2bfloat16(v11);
                __nv_bfloat162 hr0; hr0.x = h00; hr0.y = h01;
                __nv_bfloat162 hr1; hr1.x = h10; hr1.y = h11;
                __nv_bfloat162 lr0;
                lr0.x = __float2bfloat16(v00 - __bfloat162float(h00));
                lr0.y = __float2bfloat16(v01 - __bfloat162float(h01));
                __nv_bfloat162 lr1;
                lr1.x = __float2bfloat16(v10 - __bfloat162float(h10));
                lr1.y = __float2bfloat16(v11 - __bfloat162float(h11));
                *(__nv_bfloat162*)(Chi + (size_t)(m0 + r0) * E_ + n0 + c0) = hr0;
                *(__nv_bfloat162*)(Chi + (size_t)(m0 + r1) * E_ + n0 + c0) = hr1;
                *(__nv_bfloat162*)(Clo + (size_t)(m0 + r0) * E_ + n0 + c0) = lr0;
                *(__nv_bfloat162*)(Clo + (size_t)(m0 + r1) * E_ + n0 + c0) = lr1;
            } else {
                float2 w0 = {v00, v01};
                float2 w1 = {v10, v11};
                *(float2*)(C + (size_t)(m0 + r0) * E_ + n0 + c0) = w0;
                *(float2*)(C + (size_t)(m0 + r1) * E_ + n0 + c0) = w1;
            }
        }
    }
}

// ---------------- t = x @ la^T  (NROW x R) ---------------------------------
__global__ void __launch_bounds__(256) lora_rank_kernel(
    const float* __restrict__ x, const float* __restrict__ la,
    float* __restrict__ t)
{
    __shared__ float xs[E_];
    __shared__ float part[256];
    int n = blockIdx.x;
    int tid = threadIdx.x;
    const float* xr = x + (size_t)n * E_;
    for (int i = tid; i < E_; i += 256) xs[i] = xr[i];
    __syncthreads();
    int r = tid & 15, p = tid >> 4;
    float s = 0.f;
    const float* lar = la + r * E_ + p * 64;
    const float* xp  = xs + p * 64;
    #pragma unroll
    for (int i = 0; i < 64; i++) s += xp[i] * lar[i];
    part[tid] = s;
    __syncthreads();
    if (tid < 16) {
        float acc = 0.f;
        #pragma unroll
        for (int p2 = 0; p2 < 16; p2++) acc += part[p2 * 16 + tid];
        t[n * R_ + tid] = acc;
    }
}

// =================== scores via mma.sync ===================================
#define SC_TILE 18432            // 128 rows * 144 B
#define SC_SMEM (4 * SC_TILE)    // 73728 B

__global__ void __launch_bounds__(256) scores_mma(
    const __nv_bfloat16* __restrict__ qhi, const __nv_bfloat16* __restrict__ qlo,
    const __nv_bfloat16* __restrict__ khi, const __nv_bfloat16* __restrict__ klo,
    float* __restrict__ probs)
{
    extern __shared__ __align__(128) char smem[];
    const uint32_t sb = smem_u32(smem);
    int tid = threadIdx.x, wid = tid >> 5, lane = tid & 31;
    int t0 = blockIdx.x * 128, s0 = blockIdx.y * 128;
    int hj = blockIdx.z;
    int b = hj >> 4, h = hj & 15;
    size_t cbase = (size_t)b * E_ + h * HD_;
    int wm = wid >> 2, wn = wid & 3;          // 64 rows x 32 cols per warp

    const __nv_bfloat16* bases[4] = {qhi, qlo, khi, klo};
    const int rb[4] = {t0, t0, s0, s0};
    #pragma unroll
    for (int l = 0; l < 16; l++) {
        int idx = l * 256 + tid;
        int tI = l >> 2;
        int r  = (idx >> 3) & 127;
        int ch = idx & 7;
        const __nv_bfloat16* src = bases[tI] + (size_t)(rb[tI] + r) * LDQ + cbase + ch * 8;
        uint32_t dst = sb + tI * SC_TILE + r * 144 + ch * 16;
        asm volatile("cp.async.cg.shared.global [%0], [%1], 16;"
                     :: "r"(dst), "l"(src));
    }
    asm volatile("cp.async.commit_group;");
    asm volatile("cp.async.wait_group 0;");
    __syncthreads();

    int arow  = lane & 15;
    int acol8 = lane >> 4;
    int brow  = (lane & 7) + ((lane >> 4) & 1) * 8;
    int bcol8 = (lane >> 3) & 1;

    float acc[4][4][4] = {};
    #pragma unroll
    for (int s = 0; s < 4; s++) {
        uint32_t ah[4][4], al[4][4], bh[2][4], bl[2][4];
        #pragma unroll
        for (int mt = 0; mt < 4; mt++) {
            uint32_t off = (uint32_t)(wm * 64 + mt * 16 + arow) * 144
                         + (uint32_t)(s * 16 + acol8 * 8) * 2;
            LDSM_X4(ah[mt][0], ah[mt][1], ah[mt][2], ah[mt][3], sb + 0 * SC_TILE + off);
            LDSM_X4(al[mt][0], al[mt][1], al[mt][2], al[mt][3], sb + 1 * SC_TILE + off);
        }
        #pragma unroll
        for (int np = 0; np < 2; np++) {
            uint32_t off = (uint32_t)(wn * 32 + np * 16 + brow) * 144
                         + (uint32_t)(s * 16 + bcol8 * 8) * 2;
            LDSM_X4(bh[np][0], bh[np][1], bh[np][2], bh[np][3], sb + 2 * SC_TILE + off);
            LDSM_X4(bl[np][0], bl[np][1], bl[np][2], bl[np][3], sb + 3 * SC_TILE + off);
        }
        #pragma unroll
        for (int mt = 0; mt < 4; mt++)
            #pragma unroll
            for (int nt = 0; nt < 4; nt++) {
                uint32_t bh0 = bh[nt >> 1][(nt & 1) * 2];
                uint32_t bh1 = bh[nt >> 1][(nt & 1) * 2 + 1];
                uint32_t bl0 = bl[nt >> 1][(nt & 1) * 2];
                uint32_t bl1 = bl[nt >> 1][(nt & 1) * 2 + 1];
                MMA_BF16(acc[mt][nt], ah[mt], bh0, bh1);
                MMA_BF16(acc[mt][nt], ah[mt], bl0, bl1);
                MMA_BF16(acc[mt][nt], al[mt], bh0, bh1);
            }
    }

    float* pbase = probs + (size_t)hj * T_ * S_;
    int lr = lane >> 2, lc = (lane & 3) * 2;
    #pragma unroll
    for (int mt = 0; mt < 4; mt++) {
        int r0 = wm * 64 + mt * 16 + lr;
        int r1 = r0 + 8;
        #pragma unroll
        for (int nt = 0; nt < 4; nt++) {
            int c0 = wn * 32 + nt * 8 + lc;
            float2 w0 = {acc[mt][nt][0], acc[mt][nt][1]};
            float2 w1 = {acc[mt][nt][2], acc[mt][nt][3]};
            *(float2*)(pbase + (size_t)(t0 + r0) * S_ + s0 + c0) = w0;
            *(float2*)(pbase + (size_t)(t0 + r1) * S_ + s0 + c0) = w1;
        }
    }
}

// ------------- warp-per-head softmax; emits bf16 hi/lo probs ---------------
// block = (b, t), 512 threads; warp w owns head w. No block barriers.
__global__ void __launch_bounds__(512) softmax_warp_kernel(
    const float* __restrict__ probs,
    __nv_bfloat16* __restrict__ phi, __nv_bfloat16* __restrict__ plo)
{
    int t = blockIdx.x & (T_ - 1);
    int b = blockIdx.x >> 11;
    int w = threadIdx.x >> 5, lane = threadIdx.x & 31;
    size_t off = ((size_t)(b * H_ + w) * T_ + t) * S_;
    const float4* p4 = (const float4*)(probs + off);

    float4 v[16];
    float m = -1e30f;
    #pragma unroll
    for (int i = 0; i < 16; i++) {
        v[i] = p4[lane + i * 32];
        m = fmaxf(m, fmaxf(fmaxf(v[i].x, v[i].y), fmaxf(v[i].z, v[i].w)));
    }
    #pragma unroll
    for (int o = 16; o; o >>= 1) m = fmaxf(m, __shfl_xor_sync(0xffffffffu, m, o));

    float sum = 0.f;
    #pragma unroll
    for (int i = 0; i < 16; i++) {
        v[i].x = __expf(v[i].x - m);
        v[i].y = __expf(v[i].y - m);
        v[i].z = __expf(v[i].z - m);
        v[i].w = __expf(v[i].w - m);
        sum += (v[i].x + v[i].y) + (v[i].z + v[i].w);
    }
    #pragma unroll
    for (int o = 16; o; o >>= 1) sum += __shfl_xor_sync(0xffffffffu, sum, o);
    float inv = 1.0f / sum;

    #pragma unroll
    for (int i = 0; i < 16; i++) {
        float p0 = v[i].x * inv, p1 = v[i].y * inv;
        float p2 = v[i].z * inv, p3 = v[i].w * inv;
        __nv_bfloat16 h0 = __float2bfloat16(p0);
        __nv_bfloat16 h1 = __float2bfloat16(p1);
        __nv_bfloat16 h2 = __float2bfloat16(p2);
        __nv_bfloat16 h3 = __float2bfloat16(p3);
        __nv_bfloat162 ha; ha.x = h0; ha.y = h1;
        __nv_bfloat162 hb; hb.x = h2; hb.y = h3;
        __nv_bfloat162 la;
        la.x = __float2bfloat16(p0 - __bfloat162float(h0));
        la.y = __float2bfloat16(p1 - __bfloat162float(h1));
        __nv_bfloat162 lb;
        lb.x = __float2bfloat16(p2 - __bfloat162float(h2));
        lb.y = __float2bfloat16(p3 - __bfloat162float(h3));
        size_t o4 = off + (size_t)(lane + i * 32) * 4;
        *(__nv_bfloat162*)(phi + o4)     = ha;
        *(__nv_bfloat162*)(phi + o4 + 2) = hb;
        *(__nv_bfloat162*)(plo + o4)     = la;
        *(__nv_bfloat162*)(plo + o4 + 2) = lb;
    }
}

// ------------- attn_w[b,t,s] = mean_h (phi + plo) --------------------------
__global__ void __launch_bounds__(256) attn_mean_kernel(
    const __nv_bfloat16* __restrict__ phi, const __nv_bfloat16* __restrict__ plo,
    float* __restrict__ out)
{
    size_t pidx = (size_t)blockIdx.x * 256 + threadIdx.x;  // over B*T*S/4
    int s4 = (int)(pidx & (S_ / 4 - 1));                   // 512
    size_t bt = pidx >> 9;                                 // b*T + t
    int t = (int)(bt & (T_ - 1));
    int b = (int)(bt >> 11);
    size_t base = ((size_t)b * H_ * T_ + t) * S_ + (size_t)s4 * 4;

    float a0 = 0.f, a1 = 0.f, a2 = 0.f, a3 = 0.f;
    #pragma unroll
    for (int h = 0; h < H_; h++) {
        size_t o = base + (size_t)h * T_ * S_;
        __nv_bfloat162 h0 = *(const __nv_bfloat162*)(phi + o);
        __nv_bfloat162 h1 = *(const __nv_bfloat162*)(phi + o + 2);
        __nv_bfloat162 l0 = *(const __nv_bfloat162*)(plo + o);
        __nv_bfloat162 l1 = *(const __nv_bfloat162*)(plo + o + 2);
        a0 += __bfloat162float(h0.x) + __bfloat162float(l0.x);
        a1 += __bfloat162float(h0.y) + __bfloat162float(l0.y);
        a2 += __bfloat162float(h1.x) + __bfloat162float(l1.x);
        a3 += __bfloat162float(h1.y) + __bfloat162float(l1.y);
    }
    float4 o4 = {a0 * (1.0f / H_), a1 * (1.0f / H_),
                 a2 * (1.0f / H_), a3 * (1.0f / H_)};
    *(float4*)(out + bt * S_ + (size_t)s4 * 4) = o4;
}

// =================== PV via mma.sync =======================================
#define PV_PT    10240                    // P tile 128 x 80 B
#define PV_VT    4608                     // V tile 32 x 144 B
#define PV_STAGE (2*PV_PT + 2*PV_VT)      // 29696 B
#define PV_SMEM  (2*PV_STAGE)             // 59392 B

__global__ void __launch_bounds__(256) pv_mma(
    const __nv_bfloat16* __restrict__ phi, const __nv_bfloat16* __restrict__ plo,
    const __nv_bfloat16* __restrict__ vhi, const __nv_bfloat16* __restrict__ vlo,
    float* __restrict__ ao)
{
    extern __shared__ __align__(128) char smem[];
    const uint32_t sb = smem_u32(smem);
    int tid = threadIdx.x, wid = tid >> 5, lane = tid & 31;
    int t0 = blockIdx.x * 128;
    int hj = blockIdx.y;
    int b = hj >> 4, h = hj & 15;
    size_t cbase = (size_t)b * E_ + h * HD_;
    size_t poff = (size_t)hj * T_ * S_;
    int wm = wid >> 1, wn = wid & 1;          // 32 rows x 32 cols per warp

    auto load_chunk = [&](int c, int st) {
        int k0 = c * 32;
        uint32_t stage = sb + st * PV_STAGE;
        #pragma unroll
        for (int l = 0; l < 4; l++) {
            int idx = l * 256 + tid;
            int tI = l >> 1;
            int r  = (idx >> 2) & 127;
            int ch = idx & 3;
            const __nv_bfloat16* src = (tI ? plo : phi) + poff
                                     + (size_t)(t0 + r) * S_ + k0 + ch * 8;
            uint32_t dst = stage + tI * PV_PT + r * 80 + ch * 16;
            asm volatile("cp.async.cg.shared.global [%0], [%1], 16;"
                         :: "r"(dst), "l"(src));
        }
        #pragma unroll
        for (int l = 0; l < 2; l++) {
            int idx = l * 256 + tid;
            int tI = l;
            int r  = (idx >> 3) & 31;
            int ch = idx & 7;
            const __nv_bfloat16* src = (tI ? vlo : vhi)
                                     + (size_t)(k0 + r) * LDQ + cbase + ch * 8;
            uint32_t dst = stage + 2 * PV_PT + tI * PV_VT + r * 144 + ch * 16;
            asm volatile("cp.async.cg.shared.global [%0], [%1], 16;"
                         :: "r"(dst), "l"(src));
        }
        asm volatile("cp.async.commit_group;");
    };

    int arow  = lane & 15;
    int acol8 = lane >> 4;

    float acc[2][4][4] = {};

    load_chunk(0, 0);
    load_chunk(1, 1);
    asm volatile("cp.async.wait_group 1;");
    __syncthreads();

    for (int c = 0; c < S_ / 32; c++) {
        uint32_t stage = sb + (c & 1) * PV_STAGE;
        uint32_t pHiB = stage, pLoB = stage + PV_PT;
        uint32_t vHiB = stage + 2 * PV_PT, vLoB = vHiB + PV_VT;

        #pragma unroll
        for (int s = 0; s < 2; s++) {
            uint32_t ah[2][4], al[2][4], bh[2][4], bl[2][4];
            #pragma unroll
            for (int mt = 0; mt < 2; mt++) {
                uint32_t off = (uint32_t)(wm * 32 + mt * 16 + arow) * 80
                             + (uint32_t)(s * 16 + acol8 * 8) * 2;
                LDSM_X4(ah[mt][0], ah[mt][1], ah[mt][2], ah[mt][3], pHiB + off);
                LDSM_X4(al[mt][0], al[mt][1], al[mt][2], al[mt][3], pLoB + off);
            }
            #pragma unroll
            for (int np = 0; np < 2; np++) {
                uint32_t off = (uint32_t)(s * 16 + (lane & 15)) * 144
                             + (uint32_t)((lane >> 4) * 8 + wn * 32 + np * 16) * 2;
                LDSM_X4_T(bh[np][0], bh[np][1], bh[np][2], bh[np][3], vHiB + off);
                LDSM_X4_T(bl[np][0], bl[np][1], bl[np][2], bl[np][3], vLoB + off);
            }
            #pragma unroll
            for (int mt = 0; mt < 2; mt++)
                #pragma unroll
                for (int nt = 0; nt < 4; nt++) {
                    uint32_t bh0 = bh[nt >> 1][(nt & 1) * 2];
                    uint32_t bh1 = bh[nt >> 1][(nt & 1) * 2 + 1];
                    uint32_t bl0 = bl[nt >> 1][(nt & 1) * 2];
                    uint32_t bl1 = bl[nt >> 1][(nt & 1) * 2 + 1];
                    MMA_BF16(acc[mt][nt], ah[mt], bh0, bh1);
                    MMA_BF16(acc[mt][nt], ah[mt], bl0, bl1);
                    MMA_BF16(acc[mt][nt], al[mt], bh0, bh1);
                }
        }
        __syncthreads();
        if (c + 2 < S_ / 32) {
            load_chunk(c + 2, c & 1);
            asm volatile("cp.async.wait_group 1;");
        } else {
            asm volatile("cp.async.wait_group 0;");
        }
        __syncthreads();
    }

    int lr = lane >> 2, lc = (lane & 3) * 2;
    #pragma unroll
    for (int mt = 0; mt < 2; mt++) {
        int r0 = wm * 32 + mt * 16 + lr;
        int r1 = r0 + 8;
        #pragma unroll
        for (int nt = 0; nt < 4; nt++) {
            int c0 = wn * 32 + nt * 8 + lc;
            float2 w0 = {acc[mt][nt][0], acc[mt][nt][1]};
            float2 w1 = {acc[mt][nt][2], acc[mt][nt][3]};
            *(float2*)(ao + (size_t)(t0 + r0) * LDQ + cbase + c0) = w0;
            *(float2*)(ao + (size_t)(t0 + r1) * LDQ + cbase + c0) = w1;
        }
    }
}

// ---------------------------------------------------------------------------
extern "C" void kernel_launch(void* const* d_in, const int* in_sizes, int n_in,
                              void* d_out, int out_size)
{
    const float* query = (const float*)d_in[0];
    const float* key   = (const float*)d_in[1];
    const float* value = (const float*)d_in[2];
    const float* q_w  = (const float*)d_in[3];
    const float* q_b  = (const float*)d_in[4];
    const float* q_la = (const float*)d_in[5];
    const float* q_lb = (const float*)d_in[6];
    const float* k_w  = (const float*)d_in[7];
    const float* k_b  = (const float*)d_in[8];
    const float* k_la = (const float*)d_in[9];
    const float* k_lb = (const float*)d_in[10];
    const float* v_w  = (const float*)d_in[11];
    const float* v_b  = (const float*)d_in[12];
    const float* v_la = (const float*)d_in[13];
    const float* v_lb = (const float*)d_in[14];
    const float* o_w  = (const float*)d_in[15];
    const float* o_b  = (const float*)d_in[16];
    const float* o_la = (const float*)d_in[17];
    const float* o_lb = (const float*)d_in[18];

    float* out    = (float*)d_out;                 // (T,B,E)
    float* attn_w = out + (size_t)T_ * B_ * E_;    // (B,T,S)

    float *gao, *gt, *gp;
    __nv_bfloat16 *gahi, *galo, *gwhi, *gwlo;
    __nv_bfloat16 *gqhi, *gqlo, *gkhi, *gklo, *gvhi, *gvlo, *gphi, *gplo;
    cudaGetSymbolAddress((void**)&gao,  g_ao);
    cudaGetSymbolAddress((void**)&gt,   g_t);
    cudaGetSymbolAddress((void**)&gp,   g_probs);
    cudaGetSymbolAddress((void**)&gahi, g_ahi);
    cudaGetSymbolAddress((void**)&galo, g_alo);
    cudaGetSymbolAddress((void**)&gwhi, g_whi);
    cudaGetSymbolAddress((void**)&gwlo, g_wlo);
    cudaGetSymbolAddress((void**)&gqhi, g_qhi);
    cudaGetSymbolAddress((void**)&gqlo, g_qlo);
    cudaGetSymbolAddress((void**)&gkhi, g_khi);
    cudaGetSymbolAddress((void**)&gklo, g_klo);
    cudaGetSymbolAddress((void**)&gvhi, g_vhi);
    cudaGetSymbolAddress((void**)&gvlo, g_vlo);
    cudaGetSymbolAddress((void**)&gphi, g_phi);
    cudaGetSymbolAddress((void**)&gplo, g_plo);

    cudaFuncSetAttribute(gemm_lora_mma,
                         cudaFuncAttributeMaxDynamicSharedMemorySize, GM_SMEM);
    cudaFuncSetAttribute(scores_mma,
                         cudaFuncAttributeMaxDynamicSharedMemorySize, SC_SMEM);
    cudaFuncSetAttribute(pv_mma,
                         cudaFuncAttributeMaxDynamicSharedMemorySize, PV_SMEM);

    const int CVT_A_GRID = (NROW * E_) / 4 / 256;   // 4096
    const int CVT_W_GRID = (E_ * E_) / 4 / 256;     // 1024
    dim3 tc_grid(NROW / 128, E_ / 128);             // (32, 8)

    // q projection -> bf16 hi/lo (scale folded in)
    cvt_hilo_kernel<<<CVT_A_GRID, 256>>>(query, gahi, galo);
    cvt_hilo_kernel<<<CVT_W_GRID, 256>>>(q_w, gwhi, gwlo);
    lora_rank_kernel<<<NROW, 256>>>(query, q_la, gt);
    gemm_lora_mma<<<tc_grid, 256, GM_SMEM>>>(gahi, galo, gwhi, gwlo, q_b, q_lb, gt,
                                             nullptr, gqhi, gqlo, SCALE);
    // k projection -> bf16 hi/lo
    cvt_hilo_kernel<<<CVT_A_GRID, 256>>>(key, gahi, galo);
    cvt_hilo_kernel<<<CVT_W_GRID, 256>>>(k_w, gwhi, gwlo);
    lora_rank_kernel<<<NROW, 256>>>(key, k_la, gt);
    gemm_lora_mma<<<tc_grid, 256, GM_SMEM>>>(gahi, galo, gwhi, gwlo, k_b, k_lb, gt,
                                             nullptr, gkhi, gklo, 1.0f);
    // v projection -> bf16 hi/lo
    cvt_hilo_kernel<<<CVT_A_GRID, 256>>>(value, gahi, galo);
    cvt_hilo_kernel<<<CVT_W_GRID, 256>>>(v_w, gwhi, gwlo);
    lora_rank_kernel<<<NROW, 256>>>(value, v_la, gt);
    gemm_lora_mma<<<tc_grid, 256, GM_SMEM>>>(gahi, galo, gwhi, gwlo, v_b, v_lb, gt,
                                             nullptr, gvhi, gvlo, 1.0f);

    // attention
    scores_mma<<<dim3(T_/128, S_/128, B_*H_), 256, SC_SMEM>>>(gqhi, gqlo, gkhi, gklo, gp);
    softmax_warp_kernel<<<B_*T_, 512>>>(gp, gphi, gplo);
    attn_mean_kernel<<<(int)((size_t)B_*T_*S_/4/256), 256>>>(gphi, gplo, attn_w);
    pv_mma<<<dim3(T_/128, B_*H_), 256, PV_SMEM>>>(gphi, gplo, gvhi, gvlo, gao);

    // output projection (fp32 straight into d_out)
    cvt_hilo_kernel<<<CVT_A_GRID, 256>>>(gao, gahi, galo);
    cvt_hilo_kernel<<<CVT_W_GRID, 256>>>(o_w, gwhi, gwlo);
    lora_rank_kernel<<<NROW, 256>>>(gao, o_la, gt);
    gemm_lora_mma<<<tc_grid, 256, GM_SMEM>>>(gahi, galo, gwhi, gwlo, o_b, o_lb, gt,
                                             out, nullptr, nullptr, 1.0f);
}

// round 17
// speedup vs baseline: 1.0869x; 1.0869x over previous
#include <cuda_runtime.h>
#include <cuda_bf16.h>
#include <math.h>
#include <stdint.h>

#define T_   2048
#define B_   2
#define S_   2048
#define E_   1024
#define H_   16
#define HD_  64
#define R_   16
#define NROW 4096
#define LDQ  (B_*E_)
#define SCALE 0.125f

// ---------------- scratch (static device globals; no allocs allowed) --------
__device__ float g_ao[(size_t)NROW * E_];
__device__ float g_t [NROW * R_];
__device__ float g_probs[(size_t)B_ * H_ * T_ * S_];            // 512 MB fp32 scores
__device__ __nv_bfloat16 g_phi[(size_t)B_ * H_ * T_ * S_];      // 256 MB probs (mono)
__device__ __nv_bfloat16 g_ahi[(size_t)NROW * E_];
__device__ __nv_bfloat16 g_alo[(size_t)NROW * E_];
__device__ __nv_bfloat16 g_whi[(size_t)E_ * E_];
__device__ __nv_bfloat16 g_wlo[(size_t)E_ * E_];
__device__ __nv_bfloat16 g_qhi[(size_t)NROW * E_];
__device__ __nv_bfloat16 g_qlo[(size_t)NROW * E_];
__device__ __nv_bfloat16 g_khi[(size_t)NROW * E_];
__device__ __nv_bfloat16 g_klo[(size_t)NROW * E_];
__device__ __nv_bfloat16 g_vhi[(size_t)NROW * E_];
__device__ __nv_bfloat16 g_vlo[(size_t)NROW * E_];

// =================== portable tensor-core helpers ==========================
__device__ __forceinline__ uint32_t smem_u32(const void* p) {
    uint32_t a;
    asm("{ .reg .u64 t; cvta.to.shared.u64 t, %1; cvt.u32.u64 %0, t; }"
        : "=r"(a) : "l"(p));
    return a;
}

#define LDSM_X4(r0, r1, r2, r3, addr) \
    asm volatile("ldmatrix.sync.aligned.m8n8.x4.shared.b16 {%0,%1,%2,%3}, [%4];" \
                 : "=r"(r0), "=r"(r1), "=r"(r2), "=r"(r3) : "r"(addr))

#define LDSM_X4_T(r0, r1, r2, r3, addr) \
    asm volatile("ldmatrix.sync.aligned.m8n8.x4.trans.shared.b16 {%0,%1,%2,%3}, [%4];" \
                 : "=r"(r0), "=r"(r1), "=r"(r2), "=r"(r3) : "r"(addr))

#define MMA_BF16(d, a, b0v, b1v) \
    asm volatile("mma.sync.aligned.m16n8k16.row.col.f32.bf16.bf16.f32 " \
                 "{%0,%1,%2,%3}, {%4,%5,%6,%7}, {%8,%9}, {%0,%1,%2,%3};" \
                 : "+f"((d)[0]), "+f"((d)[1]), "+f"((d)[2]), "+f"((d)[3]) \
                 : "r"((a)[0]), "r"((a)[1]), "r"((a)[2]), "r"((a)[3]), \
                   "r"(b0v), "r"(b1v))

// =================== fp32 -> (bf16 hi, bf16 lo) ============================
__global__ void __launch_bounds__(256) cvt_hilo_kernel(
    const float* __restrict__ x,
    __nv_bfloat16* __restrict__ hi, __nv_bfloat16* __restrict__ lo)
{
    size_t i = ((size_t)blockIdx.x * 256 + threadIdx.x) * 4;
    float4 v = *(const float4*)(x + i);
    __nv_bfloat16 h0 = __float2bfloat16(v.x);
    __nv_bfloat16 h1 = __float2bfloat16(v.y);
    __nv_bfloat16 h2 = __float2bfloat16(v.z);
    __nv_bfloat16 h3 = __float2bfloat16(v.w);
    __nv_bfloat16 l0 = __float2bfloat16(v.x - __bfloat162float(h0));
    __nv_bfloat16 l1 = __float2bfloat16(v.y - __bfloat162float(h1));
    __nv_bfloat16 l2 = __float2bfloat16(v.z - __bfloat162float(h2));
    __nv_bfloat16 l3 = __float2bfloat16(v.w - __bfloat162float(h3));
    __nv_bfloat162* hp = (__nv_bfloat162*)(hi + i);
    __nv_bfloat162* lp = (__nv_bfloat162*)(lo + i);
    __nv_bfloat162 a; a.x = h0; a.y = h1; hp[0] = a;
    __nv_bfloat162 b; b.x = h2; b.y = h3; hp[1] = b;
    __nv_bfloat162 c; c.x = l0; c.y = l1; lp[0] = c;
    __nv_bfloat162 d; d.x = l2; d.y = l3; lp[1] = d;
}

// =================== mma.sync LoRA GEMM ====================================
#define BK      32
#define NCHUNK  (E_ / BK)          // 32
#define TILE_B  (128 * 80)         // 10240 B (rows padded to 80 B)
#define BUF_B   (4 * TILE_B)       // 40960 B per stage
#define GM_SMEM (2 * BUF_B)        // 81920 B

__global__ void __launch_bounds__(256) gemm_lora_mma(
    const __nv_bfloat16* __restrict__ Ahi, const __nv_bfloat16* __restrict__ Alo,
    const __nv_bfloat16* __restrict__ Whi, const __nv_bfloat16* __restrict__ Wlo,
    const float* __restrict__ bias, const float* __restrict__ lb,
    const float* __restrict__ t, float* __restrict__ C,
    __nv_bfloat16* __restrict__ Chi, __nv_bfloat16* __restrict__ Clo,
    float oscale)
{
    extern __shared__ __align__(128) char smem[];
    const uint32_t sb = smem_u32(smem);
    int tid = threadIdx.x, wid = tid >> 5, lane = tid & 31;
    int m0 = blockIdx.x * 128, n0 = blockIdx.y * 128;
    int wm = wid >> 2, wn = wid & 3;      // warp tile: 64 rows x 32 cols

    const __nv_bfloat16* bases[4] = {
        Ahi + (size_t)m0 * E_, Alo + (size_t)m0 * E_,
        Whi + (size_t)n0 * E_, Wlo + (size_t)n0 * E_ };

    auto load_chunk = [&](int c, int buf) {
        int k0 = c * BK;
        #pragma unroll
        for (int l = 0; l < 8; l++) {
            int idx = l * 256 + tid;
            int tI = idx >> 9;
            int r  = (idx >> 2) & 127;
            int ch = idx & 3;
            const __nv_bfloat16* src = bases[tI] + (size_t)r * E_ + k0 + ch * 8;
            uint32_t dst = sb + buf * BUF_B + tI * TILE_B + r * 80 + ch * 16;
            asm volatile("cp.async.cg.shared.global [%0], [%1], 16;"
                         :: "r"(dst), "l"(src));
        }
        asm volatile("cp.async.commit_group;");
    };

    int arow  = lane & 15;
    int acol8 = lane >> 4;
    int brow  = (lane & 7) + ((lane >> 4) & 1) * 8;
    int bcol8 = (lane >> 3) & 1;

    float acc[4][4][4] = {};

    load_chunk(0, 0);
    load_chunk(1, 1);
    asm volatile("cp.async.wait_group 1;");
    __syncthreads();

    for (int c = 0; c < NCHUNK; c++) {
        uint32_t bufb = sb + (c & 1) * BUF_B;
        uint32_t aHiB = bufb, aLoB = bufb + TILE_B;
        uint32_t wHiB = bufb + 2 * TILE_B, wLoB = bufb + 3 * TILE_B;

        #pragma unroll
        for (int s = 0; s < 2; s++) {
            uint32_t ah[4][4], al[4][4], bh[2][4], bl[2][4];
            #pragma unroll
            for (int mt = 0; mt < 4; mt++) {
                uint32_t off = (uint32_t)(wm * 64 + mt * 16 + arow) * 80
                             + (uint32_t)(s * 16 + acol8 * 8) * 2;
                LDSM_X4(ah[mt][0], ah[mt][1], ah[mt][2], ah[mt][3], aHiB + off);
                LDSM_X4(al[mt][0], al[mt][1], al[mt][2], al[mt][3], aLoB + off);
            }
            #pragma unroll
            for (int np = 0; np < 2; np++) {
                uint32_t off = (uint32_t)(wn * 32 + np * 16 + brow) * 80
                             + (uint32_t)(s * 16 + bcol8 * 8) * 2;
                LDSM_X4(bh[np][0], bh[np][1], bh[np][2], bh[np][3], wHiB + off);
                LDSM_X4(bl[np][0], bl[np][1], bl[np][2], bl[np][3], wLoB + off);
            }
            #pragma unroll
            for (int mt = 0; mt < 4; mt++)
                #pragma unroll
                for (int nt = 0; nt < 4; nt++) {
                    uint32_t bh0 = bh[nt >> 1][(nt & 1) * 2];
                    uint32_t bh1 = bh[nt >> 1][(nt & 1) * 2 + 1];
                    uint32_t bl0 = bl[nt >> 1][(nt & 1) * 2];
                    uint32_t bl1 = bl[nt >> 1][(nt & 1) * 2 + 1];
                    MMA_BF16(acc[mt][nt], ah[mt], bh0, bh1);
                    MMA_BF16(acc[mt][nt], ah[mt], bl0, bl1);
                    MMA_BF16(acc[mt][nt], al[mt], bh0, bh1);
                }
        }
        __syncthreads();
        if (c + 2 < NCHUNK) {
            load_chunk(c + 2, c & 1);
            asm volatile("cp.async.wait_group 1;");
        } else {
            asm volatile("cp.async.wait_group 0;");
        }
        __syncthreads();
    }

    // ---- epilogue: bias + t @ lb^T, fused with writeback ----
    float* Ts = (float*)smem;              // 128 x 16
    float* Ls = (float*)(smem + 8192);     // 128 x 16
    float* Bs = (float*)(smem + 16384);    // 128
    #pragma unroll
    for (int l = 0; l < 2; l++) {
        int f = tid + l * 256;
        int r = f >> 2, cc = (f & 3) * 4;
        *(float4*)(Ts + r * R_ + cc) = *(const float4*)(t  + (size_t)(m0 + r) * R_ + cc);
        *(float4*)(Ls + r * R_ + cc) = *(const float4*)(lb + (size_t)(n0 + r) * R_ + cc);
    }
    if (tid < 128) Bs[tid] = bias[n0 + tid];
    __syncthreads();

    int lr = lane >> 2, lc = (lane & 3) * 2;
    #pragma unroll
    for (int mt = 0; mt < 4; mt++) {
        int r0 = wm * 64 + mt * 16 + lr;
        int r1 = r0 + 8;
        float t0[16], t1[16];
        #pragma unroll
        for (int q = 0; q < 4; q++) {
            *(float4*)(t0 + q * 4) = *(const float4*)(Ts + r0 * R_ + q * 4);
            *(float4*)(t1 + q * 4) = *(const float4*)(Ts + r1 * R_ + q * 4);
        }
        #pragma unroll
        for (int nt = 0; nt < 4; nt++) {
            int c0 = wn * 32 + nt * 8 + lc;
            int c1 = c0 + 1;
            float e00 = 0.f, e01 = 0.f, e10 = 0.f, e11 = 0.f;
            #pragma unroll
            for (int r = 0; r < R_; r++) {
                float l0 = Ls[c0 * R_ + r], l1 = Ls[c1 * R_ + r];
                e00 += t0[r] * l0;  e01 += t0[r] * l1;
                e10 += t1[r] * l0;  e11 += t1[r] * l1;
            }
            float v00 = acc[mt][nt][0] + Bs[c0] + e00;
            float v01 = acc[mt][nt][1] + Bs[c1] + e01;
            float v10 = acc[mt][nt][2] + Bs[c0] + e10;
            float v11 = acc[mt][nt][3] + Bs[c1] + e11;
            if (Chi) {
                v00 *= oscale; v01 *= oscale; v10 *= oscale; v11 *= oscale;
                __nv_bfloat16 h00 = __float2bfloat16(v00);
                __nv_bfloat16 h01 = __float2bfloat16(v01);
                __nv_bfloat16 h10 = __float2bfloat16(v10);
                __nv_bfloat16 h11 = __float2bfloat16(v11);
                __nv_bfloat162 hr0; hr0.x = h00; hr0.y = h01;
                __nv_bfloat162 hr1; hr1.x = h10; hr1.y = h11;
                __nv_bfloat162 lr0;
                lr0.x = __float2bfloat16(v00 - __bfloat162float(h00));
                lr0.y = __float2bfloat16(v01 - __bfloat162float(h01));
                __nv_bfloat162 lr1;
                lr1.x = __float2bfloat16(v10 - __bfloat162float(h10));
                lr1.y = __float2bfloat16(v11 - __bfloat162float(h11));
                *(__nv_bfloat162*)(Chi + (size_t)(m0 + r0) * E_ + n0 + c0) = hr0;
                *(__nv_bfloat162*)(Chi + (size_t)(m0 + r1) * E_ + n0 + c0) = hr1;
                *(__nv_bfloat162*)(Clo + (size_t)(m0 + r0) * E_ + n0 + c0) = lr0;
                *(__nv_bfloat162*)(Clo + (size_t)(m0 + r1) * E_ + n0 + c0) = lr1;
            } else {
                float2 w0 = {v00, v01};
                float2 w1 = {v10, v11};
                *(float2*)(C + (size_t)(m0 + r0) * E_ + n0 + c0) = w0;
                *(float2*)(C + (size_t)(m0 + r1) * E_ + n0 + c0) = w1;
            }
        }
    }
}

// ---------------- t = x @ la^T  (NROW x R) ---------------------------------
__global__ void __launch_bounds__(256) lora_rank_kernel(
    const float* __restrict__ x, const float* __restrict__ la,
    float* __restrict__ t)
{
    __shared__ float xs[E_];
    __shared__ float part[256];
    int n = blockIdx.x;
    int tid = threadIdx.x;
    const float* xr = x + (size_t)n * E_;
    for (int i = tid; i < E_; i += 256) xs[i] = xr[i];
    __syncthreads();
    int r = tid & 15, p = tid >> 4;
    float s = 0.f;
    const float* lar = la + r * E_ + p * 64;
    const float* xp  = xs + p * 64;
    #pragma unroll
    for (int i = 0; i < 64; i++) s += xp[i] * lar[i];
    part[tid] = s;
    __syncthreads();
    if (tid < 16) {
        float acc = 0.f;
        #pragma unroll
        for (int p2 = 0; p2 < 16; p2++) acc += part[p2 * 16 + tid];
        t[n * R_ + tid] = acc;
    }
}

// =================== scores via mma.sync ===================================
#define SC_TILE 18432            // 128 rows * 144 B
#define SC_SMEM (4 * SC_TILE)    // 73728 B

__global__ void __launch_bounds__(256) scores_mma(
    const __nv_bfloat16* __restrict__ qhi, const __nv_bfloat16* __restrict__ qlo,
    const __nv_bfloat16* __restrict__ khi, const __nv_bfloat16* __restrict__ klo,
    float* __restrict__ probs)
{
    extern __shared__ __align__(128) char smem[];
    const uint32_t sb = smem_u32(smem);
    int tid = threadIdx.x, wid = tid >> 5, lane = tid & 31;
    int t0 = blockIdx.x * 128, s0 = blockIdx.y * 128;
    int hj = blockIdx.z;
    int b = hj >> 4, h = hj & 15;
    size_t cbase = (size_t)b * E_ + h * HD_;
    int wm = wid >> 2, wn = wid & 3;          // 64 rows x 32 cols per warp

    const __nv_bfloat16* bases[4] = {qhi, qlo, khi, klo};
    const int rb[4] = {t0, t0, s0, s0};
    #pragma unroll
    for (int l = 0; l < 16; l++) {
        int idx = l * 256 + tid;
        int tI = l >> 2;
        int r  = (idx >> 3) & 127;
        int ch = idx & 7;
        const __nv_bfloat16* src = bases[tI] + (size_t)(rb[tI] + r) * LDQ + cbase + ch * 8;
        uint32_t dst = sb + tI * SC_TILE + r * 144 + ch * 16;
        asm volatile("cp.async.cg.shared.global [%0], [%1], 16;"
                     :: "r"(dst), "l"(src));
    }
    asm volatile("cp.async.commit_group;");
    asm volatile("cp.async.wait_group 0;");
    __syncthreads();

    int arow  = lane & 15;
    int acol8 = lane >> 4;
    int brow  = (lane & 7) + ((lane >> 4) & 1) * 8;
    int bcol8 = (lane >> 3) & 1;

    float acc[4][4][4] = {};
    #pragma unroll
    for (int s = 0; s < 4; s++) {
        uint32_t ah[4][4], al[4][4], bh[2][4], bl[2][4];
        #pragma unroll
        for (int mt = 0; mt < 4; mt++) {
            uint32_t off = (uint32_t)(wm * 64 + mt * 16 + arow) * 144
                         + (uint32_t)(s * 16 + acol8 * 8) * 2;
            LDSM_X4(ah[mt][0], ah[mt][1], ah[mt][2], ah[mt][3], sb + 0 * SC_TILE + off);
            LDSM_X4(al[mt][0], al[mt][1], al[mt][2], al[mt][3], sb + 1 * SC_TILE + off);
        }
        #pragma unroll
        for (int np = 0; np < 2; np++) {
            uint32_t off = (uint32_t)(wn * 32 + np * 16 + brow) * 144
                         + (uint32_t)(s * 16 + bcol8 * 8) * 2;
            LDSM_X4(bh[np][0], bh[np][1], bh[np][2], bh[np][3], sb + 2 * SC_TILE + off);
            LDSM_X4(bl[np][0], bl[np][1], bl[np][2], bl[np][3], sb + 3 * SC_TILE + off);
        }
        #pragma unroll
        for (int mt = 0; mt < 4; mt++)
            #pragma unroll
            for (int nt = 0; nt < 4; nt++) {
                uint32_t bh0 = bh[nt >> 1][(nt & 1) * 2];
                uint32_t bh1 = bh[nt >> 1][(nt & 1) * 2 + 1];
                uint32_t bl0 = bl[nt >> 1][(nt & 1) * 2];
                uint32_t bl1 = bl[nt >> 1][(nt & 1) * 2 + 1];
                MMA_BF16(acc[mt][nt], ah[mt], bh0, bh1);
                MMA_BF16(acc[mt][nt], ah[mt], bl0, bl1);
                MMA_BF16(acc[mt][nt], al[mt], bh0, bh1);
            }
    }

    float* pbase = probs + (size_t)hj * T_ * S_;
    int lr = lane >> 2, lc = (lane & 3) * 2;
    #pragma unroll
    for (int mt = 0; mt < 4; mt++) {
        int r0 = wm * 64 + mt * 16 + lr;
        int r1 = r0 + 8;
        #pragma unroll
        for (int nt = 0; nt < 4; nt++) {
            int c0 = wn * 32 + nt * 8 + lc;
            float2 w0 = {acc[mt][nt][0], acc[mt][nt][1]};
            float2 w1 = {acc[mt][nt][2], acc[mt][nt][3]};
            *(float2*)(pbase + (size_t)(t0 + r0) * S_ + s0 + c0) = w0;
            *(float2*)(pbase + (size_t)(t0 + r1) * S_ + s0 + c0) = w1;
        }
    }
}

// ------------- fused softmax + head-mean; emits mono bf16 probs ------------
__global__ void __launch_bounds__(256) softmax_mean_kernel(
    const float* __restrict__ probs,
    __nv_bfloat16* __restrict__ phi, float* __restrict__ attn_w)
{
    __shared__ float red[8];
    int t = blockIdx.x & (T_ - 1);
    int b = blockIdx.x >> 11;
    int tid = threadIdx.x;
    int lane = tid & 31, wid = tid >> 5;
    float macc[8] = {};

    for (int h = 0; h < H_; ++h) {
        size_t off = ((size_t)(b * H_ + h) * T_ + t) * S_;
        const float* p = probs + off;
        float v[8];
        float m = -1e30f;
        #pragma unroll
        for (int i = 0; i < 8; i++) { v[i] = p[tid + i*256]; m = fmaxf(m, v[i]); }
        #pragma unroll
        for (int o = 16; o; o >>= 1) m = fmaxf(m, __shfl_xor_sync(0xffffffffu, m, o));
        __syncthreads();
        if (lane == 0) red[wid] = m;
        __syncthreads();
        m = red[0];
        #pragma unroll
        for (int w = 1; w < 8; w++) m = fmaxf(m, red[w]);
        float sum = 0.f;
        #pragma unroll
        for (int i = 0; i < 8; i++) { v[i] = __expf(v[i] - m); sum += v[i]; }
        #pragma unroll
        for (int o = 16; o; o >>= 1) sum += __shfl_xor_sync(0xffffffffu, sum, o);
        __syncthreads();
        if (lane == 0) red[wid] = sum;
        __syncthreads();
        sum = 0.f;
        #pragma unroll
        for (int w = 0; w < 8; w++) sum += red[w];
        float inv = 1.0f / sum;
        #pragma unroll
        for (int i = 0; i < 8; i++) {
            float pv = v[i] * inv;
            phi[off + tid + i*256] = __float2bfloat16(pv);
            macc[i] += pv;
        }
    }
    float* ow = attn_w + ((size_t)b * T_ + t) * S_;
    #pragma unroll
    for (int i = 0; i < 8; i++) ow[tid + i*256] = macc[i] * (1.0f / H_);
}

// =================== PV via mma.sync (mono P, hi/lo V) =====================
#define PV_PT    10240                    // P tile 128 x 80 B
#define PV_VT    4608                     // V tile 32 x 144 B
#define PV_STAGE (PV_PT + 2*PV_VT)        // 19456 B
#define PV_SMEM  (2*PV_STAGE)             // 38912 B

__global__ void __launch_bounds__(256) pv_mma(
    const __nv_bfloat16* __restrict__ phi,
    const __nv_bfloat16* __restrict__ vhi, const __nv_bfloat16* __restrict__ vlo,
    float* __restrict__ ao)
{
    extern __shared__ __align__(128) char smem[];
    const uint32_t sb = smem_u32(smem);
    int tid = threadIdx.x, wid = tid >> 5, lane = tid & 31;
    int t0 = blockIdx.x * 128;
    int hj = blockIdx.y;
    int b = hj >> 4, h = hj & 15;
    size_t cbase = (size_t)b * E_ + h * HD_;
    size_t poff = (size_t)hj * T_ * S_;
    int wm = wid >> 1, wn = wid & 1;          // 32 rows x 32 cols per warp

    auto load_chunk = [&](int c, int st) {
        int k0 = c * 32;
        uint32_t stage = sb + st * PV_STAGE;
        #pragma unroll
        for (int l = 0; l < 2; l++) {
            int idx = l * 256 + tid;
            int r  = (idx >> 2) & 127;
            int ch = idx & 3;
            const __nv_bfloat16* src = phi + poff
                                     + (size_t)(t0 + r) * S_ + k0 + ch * 8;
            uint32_t dst = stage + r * 80 + ch * 16;
            asm volatile("cp.async.cg.shared.global [%0], [%1], 16;"
                         :: "r"(dst), "l"(src));
        }
        #pragma unroll
        for (int l = 0; l < 2; l++) {
            int idx = l * 256 + tid;
            int tI = l;
            int r  = (idx >> 3) & 31;
            int ch = idx & 7;
            const __nv_bfloat16* src = (tI ? vlo : vhi)
                                     + (size_t)(k0 + r) * LDQ + cbase + ch * 8;
            uint32_t dst = stage + PV_PT + tI * PV_VT + r * 144 + ch * 16;
            asm volatile("cp.async.cg.shared.global [%0], [%1], 16;"
                         :: "r"(dst), "l"(src));
        }
        asm volatile("cp.async.commit_group;");
    };

    int arow  = lane & 15;
    int acol8 = lane >> 4;

    float acc[2][4][4] = {};

    load_chunk(0, 0);
    load_chunk(1, 1);
    asm volatile("cp.async.wait_group 1;");
    __syncthreads();

    for (int c = 0; c < S_ / 32; c++) {
        uint32_t stage = sb + (c & 1) * PV_STAGE;
        uint32_t pB = stage;
        uint32_t vHiB = stage + PV_PT, vLoB = vHiB + PV_VT;

        #pragma unroll
        for (int s = 0; s < 2; s++) {
            uint32_t ah[2][4], bh[2][4], bl[2][4];
            #pragma unroll
            for (int mt = 0; mt < 2; mt++) {
                uint32_t off = (uint32_t)(wm * 32 + mt * 16 + arow) * 80
                             + (uint32_t)(s * 16 + acol8 * 8) * 2;
                LDSM_X4(ah[mt][0], ah[mt][1], ah[mt][2], ah[mt][3], pB + off);
            }
            #pragma unroll
            for (int np = 0; np < 2; np++) {
                uint32_t off = (uint32_t)(s * 16 + (lane & 15)) * 144
                             + (uint32_t)((lane >> 4) * 8 + wn * 32 + np * 16) * 2;
                LDSM_X4_T(bh[np][0], bh[np][1], bh[np][2], bh[np][3], vHiB + off);
                LDSM_X4_T(bl[np][0], bl[np][1], bl[np][2], bl[np][3], vLoB + off);
            }
            #pragma unroll
            for (int mt = 0; mt < 2; mt++)
                #pragma unroll
                for (int nt = 0; nt < 4; nt++) {
                    uint32_t bh0 = bh[nt >> 1][(nt & 1) * 2];
                    uint32_t bh1 = bh[nt >> 1][(nt & 1) * 2 + 1];
                    uint32_t bl0 = bl[nt >> 1][(nt & 1) * 2];
                    uint32_t bl1 = bl[nt >> 1][(nt & 1) * 2 + 1];
                    MMA_BF16(acc[mt][nt], ah[mt], bh0, bh1);
                    MMA_BF16(acc[mt][nt], ah[mt], bl0, bl1);
                }
        }
        __syncthreads();
        if (c + 2 < S_ / 32) {
            load_chunk(c + 2, c & 1);
            asm volatile("cp.async.wait_group 1;");
        } else {
            asm volatile("cp.async.wait_group 0;");
        }
        __syncthreads();
    }

    int lr = lane >> 2, lc = (lane & 3) * 2;
    #pragma unroll
    for (int mt = 0; mt < 2; mt++) {
        int r0 = wm * 32 + mt * 16 + lr;
        int r1 = r0 + 8;
        #pragma unroll
        for (int nt = 0; nt < 4; nt++) {
            int c0 = wn * 32 + nt * 8 + lc;
            float2 w0 = {acc[mt][nt][0], acc[mt][nt][1]};
            float2 w1 = {acc[mt][nt][2], acc[mt][nt][3]};
            *(float2*)(ao + (size_t)(t0 + r0) * LDQ + cbase + c0) = w0;
            *(float2*)(ao + (size_t)(t0 + r1) * LDQ + cbase + c0) = w1;
        }
    }
}

// ---------------------------------------------------------------------------
extern "C" void kernel_launch(void* const* d_in, const int* in_sizes, int n_in,
                              void* d_out, int out_size)
{
    const float* query = (const float*)d_in[0];
    const float* key   = (const float*)d_in[1];
    const float* value = (const float*)d_in[2];
    const float* q_w  = (const float*)d_in[3];
    const float* q_b  = (const float*)d_in[4];
    const float* q_la = (const float*)d_in[5];
    const float* q_lb = (const float*)d_in[6];
    const float* k_w  = (const float*)d_in[7];
    const float* k_b  = (const float*)d_in[8];
    const float* k_la = (const float*)d_in[9];
    const float* k_lb = (const float*)d_in[10];
    const float* v_w  = (const float*)d_in[11];
    const float* v_b  = (const float*)d_in[12];
    const float* v_la = (const float*)d_in[13];
    const float* v_lb = (const float*)d_in[14];
    const float* o_w  = (const float*)d_in[15];
    const float* o_b  = (const float*)d_in[16];
    const float* o_la = (const float*)d_in[17];
    const float* o_lb = (const float*)d_in[18];

    float* out    = (float*)d_out;                 // (T,B,E)
    float* attn_w = out + (size_t)T_ * B_ * E_;    // (B,T,S)

    float *gao, *gt, *gp;
    __nv_bfloat16 *gahi, *galo, *gwhi, *gwlo;
    __nv_bfloat16 *gqhi, *gqlo, *gkhi, *gklo, *gvhi, *gvlo, *gphi;
    cudaGetSymbolAddress((void**)&gao,  g_ao);
    cudaGetSymbolAddress((void**)&gt,   g_t);
    cudaGetSymbolAddress((void**)&gp,   g_probs);
    cudaGetSymbolAddress((void**)&gahi, g_ahi);
    cudaGetSymbolAddress((void**)&galo, g_alo);
    cudaGetSymbolAddress((void**)&gwhi, g_whi);
    cudaGetSymbolAddress((void**)&gwlo, g_wlo);
    cudaGetSymbolAddress((void**)&gqhi, g_qhi);
    cudaGetSymbolAddress((void**)&gqlo, g_qlo);
    cudaGetSymbolAddress((void**)&gkhi, g_khi);
    cudaGetSymbolAddress((void**)&gklo, g_klo);
    cudaGetSymbolAddress((void**)&gvhi, g_vhi);
    cudaGetSymbolAddress((void**)&gvlo, g_vlo);
    cudaGetSymbolAddress((void**)&gphi, g_phi);

    cudaFuncSetAttribute(gemm_lora_mma,
                         cudaFuncAttributeMaxDynamicSharedMemorySize, GM_SMEM);
    cudaFuncSetAttribute(scores_mma,
                         cudaFuncAttributeMaxDynamicSharedMemorySize, SC_SMEM);
    cudaFuncSetAttribute(pv_mma,
                         cudaFuncAttributeMaxDynamicSharedMemorySize, PV_SMEM);

    const int CVT_A_GRID = (NROW * E_) / 4 / 256;   // 4096
    const int CVT_W_GRID = (E_ * E_) / 4 / 256;     // 1024
    dim3 tc_grid(NROW / 128, E_ / 128);             // (32, 8)

    // q projection -> bf16 hi/lo (scale folded in)
    cvt_hilo_kernel<<<CVT_A_GRID, 256>>>(query, gahi, galo);
    cvt_hilo_kernel<<<CVT_W_GRID, 256>>>(q_w, gwhi, gwlo);
    lora_rank_kernel<<<NROW, 256>>>(query, q_la, gt);
    gemm_lora_mma<<<tc_grid, 256, GM_SMEM>>>(gahi, galo, gwhi, gwlo, q_b, q_lb, gt,
                                             nullptr, gqhi, gqlo, SCALE);
    // k projection -> bf16 hi/lo
    cvt_hilo_kernel<<<CVT_A_GRID, 256>>>(key, gahi, galo);
    cvt_hilo_kernel<<<CVT_W_GRID, 256>>>(k_w, gwhi, gwlo);
    lora_rank_kernel<<<NROW, 256>>>(key, k_la, gt);
    gemm_lora_mma<<<tc_grid, 256, GM_SMEM>>>(gahi, galo, gwhi, gwlo, k_b, k_lb, gt,
                                             nullptr, gkhi, gklo, 1.0f);
    // v projection -> bf16 hi/lo
    cvt_hilo_kernel<<<CVT_A_GRID, 256>>>(value, gahi, galo);
    cvt_hilo_kernel<<<CVT_W_GRID, 256>>>(v_w, gwhi, gwlo);
    lora_rank_kernel<<<NROW, 256>>>(value, v_la, gt);
    gemm_lora_mma<<<tc_grid, 256, GM_SMEM>>>(gahi, galo, gwhi, gwlo, v_b, v_lb, gt,
                                             nullptr, gvhi, gvlo, 1.0f);

    // attention
    scores_mma<<<dim3(T_/128, S_/128, B_*H_), 256, SC_SMEM>>>(gqhi, gqlo, gkhi, gklo, gp);
    softmax_mean_kernel<<<B_*T_, 256>>>(gp, gphi, attn_w);
    pv_mma<<<dim3(T_/128, B_*H_), 256, PV_SMEM>>>(gphi, gvhi, gvlo, gao);

    // output projection (fp32 straight into d_out)
    cvt_hilo_kernel<<<CVT_A_GRID, 256>>>(gao, gahi, galo);
    cvt_hilo_kernel<<<CVT_W_GRID, 256>>>(o_w, gwhi, gwlo);
    lora_rank_kernel<<<NROW, 256>>>(gao, o_la, gt);
    gemm_lora_mma<<<tc_grid, 256, GM_SMEM>>>(gahi, galo, gwhi, gwlo, o_b, o_lb, gt,
                                             out, nullptr, nullptr, 1.0f);
}